// round 16
// baseline (speedup 1.0000x reference)
#include <cuda_runtime.h>
#include <cuda_bf16.h>
#include <math.h>
#include <stdint.h>

#define NB      2
#define SEQ     2048
#define DMODEL  512
#define VOCAB   32000
#define NHEADS  8
#define DHEAD   64
#define DFFN    2048
#define NDEPTH  6
#define MROWS   (NB*SEQ)   /* 4096 */

#define RES_SCALE 1.86120971820393f
#define ATTN_SCALE 8.0f
#define LN_EPS 1e-5f

/* ---------------- scratch ---------------- */
__device__ float g_h [MROWS*DMODEL];
__device__ float g_hr[MROWS*DMODEL];
__device__ float g_q [MROWS*DMODEL];
__device__ float g_k [MROWS*DMODEL];
__device__ float g_v [MROWS*DMODEL];
__device__ float g_a [MROWS*DMODEL];
__device__ float g_t [MROWS*DMODEL];
__device__ float g_ff[MROWS*DFFN];

/* pair-interleaved packed weights (R12 layout) */
#define BLKF    4224
#define PLF_D   270336
#define PLF_F   1081344
#define WOFF_Q  0
#define WOFF_K  1622016
#define WOFF_V  3244032
#define WOFF_O  4866048
#define WOFF_1  6488064
#define WOFF_2  12976128
#define WOFF_L  19464192
#define WTOTAL  36360192
__device__ float g_w[WTOTAL];

__device__ __forceinline__ float tf32r(float x) {
    unsigned u;
    asm("cvt.rna.tf32.f32 %0, %1;" : "=r"(u) : "f"(x));
    return __uint_as_float(u);
}
__device__ __forceinline__ uint32_t smem_u32(const void* p) {
    uint32_t a;
    asm("{ .reg .u64 t; cvta.to.shared.u64 t, %1; cvt.u32.u64 %0, t; }" : "=r"(a) : "l"(p));
    return a;
}
__device__ __forceinline__ void cpa16(uint32_t dst, const void* src) {
    asm volatile("cp.async.cg.shared.global [%0], [%1], 16;" :: "r"(dst), "l"(src));
}
__device__ __forceinline__ void mma_tf32(float* d, const unsigned* a, unsigned b0, unsigned b1) {
    asm volatile(
        "mma.sync.aligned.m16n8k8.row.col.f32.tf32.tf32.f32 "
        "{%0,%1,%2,%3},{%4,%5,%6,%7},{%8,%9},{%0,%1,%2,%3};"
        : "+f"(d[0]), "+f"(d[1]), "+f"(d[2]), "+f"(d[3])
        : "r"(a[0]), "r"(a[1]), "r"(a[2]), "r"(a[3]), "r"(b0), "r"(b1));
}

/* ======== prep: pack weights + embed ======== */
#define PB0  811008u
#define PB1  1622016u
#define PB2  2433024u
#define PB3  3244032u
#define PB4  6488064u
#define PB5  9732096u
#define PB6  18180096u
#define PB7  19228672u

__device__ __forceinline__ void wpack(const float* __restrict__ src, float2* __restrict__ dst,
                                      unsigned rel, int K, int N, unsigned blocksPerLayer) {
    unsigned block = rel / 2112u, w = rel - block * 2112u;
    unsigned row = w / 132u, np = w - row * 132u;
    unsigned nb128 = (unsigned)N >> 7;
    unsigned lay = block / blocksPerLayer, bl = block - lay * blocksPerLayer;
    unsigned s = bl / nb128, nb = bl - s * nb128;
    unsigned ks = row >> 2, tg = row & 3;
    float2 o = make_float2(0.0f, 0.0f);
    if (np < 128u) {
        size_t base = (size_t)lay * K * N + (size_t)(s * 32 + ks * 8 + tg) * N + nb * 128 + np;
        o.x = tf32r(src[base]);
        o.y = tf32r(src[base + (size_t)4 * N]);
    }
    dst[rel] = o;
}

__global__ __launch_bounds__(256) void prep_kernel(
    const int* __restrict__ x, const float* __restrict__ tok, const float* __restrict__ pos,
    const float* __restrict__ Wq, const float* __restrict__ Wk, const float* __restrict__ Wv,
    const float* __restrict__ Wo, const float* __restrict__ W1, const float* __restrict__ W2,
    const float* __restrict__ Wl, float* __restrict__ wout,
    float2* __restrict__ h2, float2* __restrict__ hr2) {
    unsigned i = blockIdx.x * 256 + threadIdx.x;
    if (i < PB6) {
        if (i < PB3) {
            if (i < PB0)      wpack(Wq, (float2*)(wout + WOFF_Q), i,        DMODEL, DMODEL, 64);
            else if (i < PB1) wpack(Wk, (float2*)(wout + WOFF_K), i - PB0,  DMODEL, DMODEL, 64);
            else if (i < PB2) wpack(Wv, (float2*)(wout + WOFF_V), i - PB1,  DMODEL, DMODEL, 64);
            else              wpack(Wo, (float2*)(wout + WOFF_O), i - PB2,  DMODEL, DMODEL, 64);
        } else if (i < PB4)   wpack(W1, (float2*)(wout + WOFF_1), i - PB3,  DMODEL, DFFN,   256);
        else if (i < PB5)     wpack(W2, (float2*)(wout + WOFF_2), i - PB4,  DFFN,   DMODEL, 256);
        else                  wpack(Wl, (float2*)(wout + WOFF_L), i - PB5,  DMODEL, VOCAB,  4000);
    } else {
        unsigned e = i - PB6;
        int row = e >> 8;
        int d2  = e & 255;
        int n   = row & (SEQ - 1);
        const float* tp = tok + (size_t)x[row] * DMODEL + d2 * 2;
        const float* pp = pos + (size_t)n * DMODEL + d2 * 2;
        float2 v = make_float2(tp[0] + pp[0], tp[1] + pp[1]);
        h2[e] = v;
        hr2[e] = make_float2(tf32r(v.x), tf32r(v.y));
    }
}

/* ================= TF32 mma.sync GEMM, 2-stage cp.async pipeline =========
   wait_group 0 / barrier / stage(it+1) / compute(it): stage(it+1) overlaps
   compute(it). Small variant: 52KB smem -> 4 CTAs/SM (16 warps). */
#define AST     36
#define G_SMEM_L (2*(128*AST+BLKF)*4)   /* 70656 B */
#define G_SMEM_S (2*(64*AST+BLKF)*4)    /* 52224 B */

template<int EPI, int BM, int T>
__device__ __forceinline__ void gemm_body(const float* __restrict__ A,
                                          const float* __restrict__ B,
                                          float* __restrict__ C,
                                          int N, int K, float* sm) {
    constexpr int ASTG   = BM * AST;
    constexpr int STAGEF = ASTG + BLKF;
    constexpr int AITER  = BM * 8 / T;
    constexpr int BITER  = (1056 + T - 1) / T;

    int tid = threadIdx.x;
    int warp = tid >> 5, lane = tid & 31;
    int wm = warp >> 1, wn = warp & 1;
    int g = lane >> 2, tg = lane & 3;
    int bm = blockIdx.y * BM;
    int bn = blockIdx.x * 128;
    int nb128 = N >> 7;

    uint32_t sb = smem_u32(sm);

    float acc[2][8][4];
#pragma unroll
    for (int i = 0; i < 2; i++)
#pragma unroll
        for (int j = 0; j < 8; j++)
#pragma unroll
            for (int t = 0; t < 4; t++) acc[i][j][t] = 0.0f;

    int nIter = K >> 5;

#define STAGE(slot, k0)                                                          \
    do {                                                                         \
        uint32_t as_ = sb + (uint32_t)(slot) * (STAGEF * 4);                     \
        uint32_t bs_ = as_ + ASTG * 4;                                           \
        _Pragma("unroll")                                                        \
        for (int it_ = 0; it_ < AITER; it_++) {                                  \
            int id_ = tid + it_ * T;                                             \
            int r_ = id_ >> 3, c4_ = (id_ & 7) * 4;                              \
            cpa16(as_ + (r_ * AST + c4_) * 4,                                    \
                  A + (size_t)(bm + r_) * K + (k0) + c4_);                       \
        }                                                                        \
        const float* Bb_ = B + ((size_t)((k0) >> 5) * nb128 + blockIdx.x) * BLKF; \
        _Pragma("unroll")                                                        \
        for (int it_ = 0; it_ < BITER; it_++) {                                  \
            int id_ = tid + it_ * T;                                             \
            if (id_ < 1056) cpa16(bs_ + id_ * 16, Bb_ + id_ * 4);                \
        }                                                                        \
        asm volatile("cp.async.commit_group;" ::: "memory");                     \
    } while (0)

    STAGE(0, 0);

    for (int it = 0; it < nIter; it++) {
        asm volatile("cp.async.wait_group 0;" ::: "memory");
        __syncthreads();
        if (it + 1 < nIter) STAGE((it + 1) & 1, (it + 1) * 32);

        int slot = it & 1;
        const float*  as = sm + slot * STAGEF;
        const float2* b2 = (const float2*)(as + ASTG);

#pragma unroll
        for (int ks = 0; ks < 4; ks++) {
            int k8 = ks * 8;
            int rb = (ks * 4 + tg) * 132;
            unsigned af[2][4];
#pragma unroll
            for (int i = 0; i < 2; i++) {
                int mr = wm * 32 + i * 16 + g;
                af[i][0] = __float_as_uint(as[mr * AST + k8 + tg]);
                af[i][1] = __float_as_uint(as[(mr + 8) * AST + k8 + tg]);
                af[i][2] = __float_as_uint(as[mr * AST + k8 + tg + 4]);
                af[i][3] = __float_as_uint(as[(mr + 8) * AST + k8 + tg + 4]);
            }
#pragma unroll
            for (int j = 0; j < 8; j++) {
                int nc = wn * 64 + j * 8 + g;
                float2 bv = b2[rb + nc];
                unsigned b0 = __float_as_uint(bv.x);
                unsigned b1 = __float_as_uint(bv.y);
                mma_tf32(acc[0][j], af[0], b0, b1);
                mma_tf32(acc[1][j], af[1], b0, b1);
            }
        }
    }
#undef STAGE

    if (EPI == 2) {
        __syncthreads();
#pragma unroll
        for (int i = 0; i < 2; i++) {
            float ss0 = 0.0f, ss1 = 0.0f;
#pragma unroll
            for (int j = 0; j < 8; j++) {
                ss0 += acc[i][j][0] * acc[i][j][0] + acc[i][j][1] * acc[i][j][1];
                ss1 += acc[i][j][2] * acc[i][j][2] + acc[i][j][3] * acc[i][j][3];
            }
            ss0 += __shfl_xor_sync(0xffffffffu, ss0, 1);
            ss0 += __shfl_xor_sync(0xffffffffu, ss0, 2);
            ss1 += __shfl_xor_sync(0xffffffffu, ss1, 1);
            ss1 += __shfl_xor_sync(0xffffffffu, ss1, 2);
            float n0 = 1.0f / fmaxf(sqrtf(ss0), 1e-12f);
            float n1 = 1.0f / fmaxf(sqrtf(ss1), 1e-12f);
#pragma unroll
            for (int j = 0; j < 8; j++) {
                acc[i][j][0] *= n0; acc[i][j][1] *= n0;
                acc[i][j][2] *= n1; acc[i][j][3] *= n1;
            }
        }
    }

#pragma unroll
    for (int i = 0; i < 2; i++) {
        int r0 = bm + wm * 32 + i * 16 + g;
#pragma unroll
        for (int j = 0; j < 8; j++) {
            int col = bn + wn * 64 + j * 8 + tg * 2;
            float v0 = acc[i][j][0], v1 = acc[i][j][1];
            float v2 = acc[i][j][2], v3 = acc[i][j][3];
            if (EPI == 1) {
                v0 = tf32r(0.5f * v0 * (1.0f + erff(v0 * 0.70710678118654752f)));
                v1 = tf32r(0.5f * v1 * (1.0f + erff(v1 * 0.70710678118654752f)));
                v2 = tf32r(0.5f * v2 * (1.0f + erff(v2 * 0.70710678118654752f)));
                v3 = tf32r(0.5f * v3 * (1.0f + erff(v3 * 0.70710678118654752f)));
            } else if (EPI == 2 || EPI == 3) {
                v0 = tf32r(v0); v1 = tf32r(v1); v2 = tf32r(v2); v3 = tf32r(v3);
            }
            *(float2*)&C[(size_t)r0 * N + col]       = make_float2(v0, v1);
            *(float2*)&C[(size_t)(r0 + 8) * N + col] = make_float2(v2, v3);
        }
    }
}

template<int EPI>
__global__ __launch_bounds__(256, 2) void gemm_tc(const float* __restrict__ A,
                                                  const float* __restrict__ B,
                                                  float* __restrict__ C, int N, int K) {
    extern __shared__ float sm[];
    gemm_body<EPI, 128, 256>(A, B, C, N, K, sm);
}

template<int EPI>
__global__ __launch_bounds__(128, 4) void gemm_sm(const float* __restrict__ A,
                                                  const float* __restrict__ B,
                                                  float* __restrict__ C, int N, int K) {
    extern __shared__ float sm[];
    gemm_body<EPI, 64, 128>(A, B, C, N, K, sm);
}

__global__ __launch_bounds__(128, 4) void gemm_qkv(const float* __restrict__ A,
                                                   const float* __restrict__ B0,
                                                   const float* __restrict__ B1,
                                                   const float* __restrict__ B2,
                                                   float* __restrict__ C0,
                                                   float* __restrict__ C1,
                                                   float* __restrict__ C2,
                                                   int N, int K) {
    extern __shared__ float sm[];
    if (blockIdx.z == 0)      gemm_body<2, 64, 128>(A, B0, C0, N, K, sm);
    else if (blockIdx.z == 1) gemm_body<2, 64, 128>(A, B1, C1, N, K, sm);
    else                      gemm_body<3, 64, 128>(A, B2, C2, N, K, sm);
}

/* ================= TF32 flash attention (R15, kept) ================= */
#define KPAD 68
#define VPAD 72
#define KS_F (64*KPAD)
#define VS_F (64*VPAD)
#define ATTN_SMEM ((2*KS_F + 2*VS_F + 64*72) * 4)

__global__ __launch_bounds__(128, 2) void attn_tc(const float* __restrict__ q,
                                                  const float* __restrict__ k,
                                                  const float* __restrict__ v,
                                                  float* __restrict__ o) {
    extern __shared__ float sm[];
    float* Ks0 = sm;
    float* Vs0 = sm + 2 * KS_F;
    float* Ps  = sm + 2 * KS_F + 2 * VS_F;
    uint32_t sb = smem_u32(sm);

    int qt = gridDim.x - 1 - blockIdx.x;
    int hh = blockIdx.y, b = blockIdx.z;
    int tid = threadIdx.x, warp = tid >> 5, lane = tid & 31;
    int g = lane >> 2, tg = lane & 3;

    unsigned qf[8][4];
    const float* qbase = q + (size_t)(b * SEQ + qt * 64 + warp * 16 + g) * DMODEL + hh * 64;
#pragma unroll
    for (int kk = 0; kk < 8; kk++) {
        qf[kk][0] = __float_as_uint(qbase[kk * 8 + tg]);
        qf[kk][1] = __float_as_uint(qbase[(size_t)8 * DMODEL + kk * 8 + tg]);
        qf[kk][2] = __float_as_uint(qbase[kk * 8 + tg + 4]);
        qf[kk][3] = __float_as_uint(qbase[(size_t)8 * DMODEL + kk * 8 + tg + 4]);
    }

    float oa[8][4];
#pragma unroll
    for (int j = 0; j < 8; j++)
#pragma unroll
        for (int t = 0; t < 4; t++) oa[j][t] = 0.0f;
    float l0 = 0.0f, l1 = 0.0f;

    int prow0 = (warp * 16 + g) * 72;
    int prow1 = (warp * 16 + g + 8) * 72;

#define ASTAGE_TILE(kt_, bb_)                                                    \
    do {                                                                         \
        uint32_t ka_ = sb + (uint32_t)(bb_) * (KS_F * 4);                        \
        uint32_t va_ = sb + (2 * KS_F + (bb_) * VS_F) * 4;                       \
        _Pragma("unroll")                                                        \
        for (int it_ = 0; it_ < 8; it_++) {                                      \
            int i_ = tid + it_ * 128;                                            \
            int r_ = i_ >> 4, c4_ = (i_ & 15) * 4;                               \
            size_t gg_ = (size_t)(b * SEQ + (kt_) * 64 + r_) * DMODEL + hh * 64 + c4_; \
            cpa16(ka_ + (r_ * KPAD + c4_) * 4, k + gg_);                         \
            cpa16(va_ + (r_ * VPAD + c4_) * 4, v + gg_);                         \
        }                                                                        \
        asm volatile("cp.async.commit_group;" ::: "memory");                     \
    } while (0)

    ASTAGE_TILE(0, 0);

    for (int kt = 0; kt <= qt; kt++) {
        int bb = kt & 1;
        asm volatile("cp.async.wait_group 0;" ::: "memory");
        __syncthreads();
        if (kt < qt) ASTAGE_TILE(kt + 1, bb ^ 1);

        const float* Ks = Ks0 + bb * KS_F;
        const float* Vs = Vs0 + bb * VS_F;

        float s[8][4];
#pragma unroll
        for (int j = 0; j < 8; j++)
#pragma unroll
            for (int t = 0; t < 4; t++) s[j][t] = 0.0f;
#pragma unroll
        for (int kk = 0; kk < 8; kk++) {
            int d0 = kk * 8 + tg, d1 = d0 + 4;
#pragma unroll
            for (int j = 0; j < 8; j++) {
                const float* krow = Ks + (j * 8 + g) * KPAD;
                unsigned b0 = __float_as_uint(krow[d0]);
                unsigned b1 = __float_as_uint(krow[d1]);
                mma_tf32(s[j], qf[kk], b0, b1);
            }
        }

        if (kt == qt) {
            int r0 = warp * 16 + g, r1 = r0 + 8;
#pragma unroll
            for (int j = 0; j < 8; j++) {
                int c0 = j * 8 + tg * 2, c1 = c0 + 1;
                if (c0 > r0) s[j][0] = -1e30f;
                if (c1 > r0) s[j][1] = -1e30f;
                if (c0 > r1) s[j][2] = -1e30f;
                if (c1 > r1) s[j][3] = -1e30f;
            }
        }

        float sum0 = 0.0f, sum1 = 0.0f;
#pragma unroll
        for (int j = 0; j < 8; j++) {
            int c0 = j * 8 + tg * 2;
            float e0 = __expf(fmaf(s[j][0], ATTN_SCALE, -ATTN_SCALE));
            float e1 = __expf(fmaf(s[j][1], ATTN_SCALE, -ATTN_SCALE));
            float e2 = __expf(fmaf(s[j][2], ATTN_SCALE, -ATTN_SCALE));
            float e3 = __expf(fmaf(s[j][3], ATTN_SCALE, -ATTN_SCALE));
            sum0 += e0 + e1;
            sum1 += e2 + e3;
            *(float2*)&Ps[prow0 + c0] = make_float2(e0, e1);
            *(float2*)&Ps[prow1 + c0] = make_float2(e2, e3);
        }
        sum0 += __shfl_xor_sync(0xffffffffu, sum0, 1);
        sum0 += __shfl_xor_sync(0xffffffffu, sum0, 2);
        sum1 += __shfl_xor_sync(0xffffffffu, sum1, 1);
        sum1 += __shfl_xor_sync(0xffffffffu, sum1, 2);
        l0 += sum0;
        l1 += sum1;
        __syncwarp();

#pragma unroll
        for (int kk = 0; kk < 8; kk++) {
            unsigned a[4];
            a[0] = __float_as_uint(Ps[prow0 + kk * 8 + tg]);
            a[1] = __float_as_uint(Ps[prow1 + kk * 8 + tg]);
            a[2] = __float_as_uint(Ps[prow0 + kk * 8 + tg + 4]);
            a[3] = __float_as_uint(Ps[prow1 + kk * 8 + tg + 4]);
#pragma unroll
            for (int j = 0; j < 8; j++) {
                unsigned b0 = __float_as_uint(Vs[(kk * 8 + tg)     * VPAD + j * 8 + g]);
                unsigned b1 = __float_as_uint(Vs[(kk * 8 + tg + 4) * VPAD + j * 8 + g]);
                mma_tf32(oa[j], a, b0, b1);
            }
        }
    }
#undef ASTAGE_TILE

    float inv0 = 1.0f / l0, inv1 = 1.0f / l1;
    size_t orow0 = (size_t)(b * SEQ + qt * 64 + warp * 16 + g) * DMODEL + hh * 64;
    size_t orow1 = orow0 + (size_t)8 * DMODEL;
#pragma unroll
    for (int j = 0; j < 8; j++) {
        int c0 = j * 8 + tg * 2;
        *(float2*)&o[orow0 + c0] = make_float2(tf32r(oa[j][0] * inv0), tf32r(oa[j][1] * inv0));
        *(float2*)&o[orow1 + c0] = make_float2(tf32r(oa[j][2] * inv1), tf32r(oa[j][3] * inv1));
    }
}

/* ---------------- residual + LayerNorm: one warp per row ---------------- */
__global__ __launch_bounds__(256) void ln_res_kernel(
        float* __restrict__ h, const float* __restrict__ a,
        const float* __restrict__ g, const float* __restrict__ bb,
        float* __restrict__ hr) {
    int warp = threadIdx.x >> 5, lane = threadIdx.x & 31;
    int row = blockIdx.x * 8 + warp;
    size_t base = (size_t)row * DMODEL;

    float4 xv[4];
    float s = 0.0f;
#pragma unroll
    for (int i = 0; i < 4; i++) {
        int c = i * 128 + lane * 4;
        float4 hv = *(const float4*)&h[base + c];
        float4 av = *(const float4*)&a[base + c];
        xv[i].x = fmaf(RES_SCALE, hv.x, av.x);
        xv[i].y = fmaf(RES_SCALE, hv.y, av.y);
        xv[i].z = fmaf(RES_SCALE, hv.z, av.z);
        xv[i].w = fmaf(RES_SCALE, hv.w, av.w);
        s += (xv[i].x + xv[i].y) + (xv[i].z + xv[i].w);
    }
#pragma unroll
    for (int o2 = 16; o2; o2 >>= 1) s += __shfl_xor_sync(0xffffffffu, s, o2);
    float mean = s * (1.0f / DMODEL);

    float vv = 0.0f;
#pragma unroll
    for (int i = 0; i < 4; i++) {
        xv[i].x -= mean; xv[i].y -= mean; xv[i].z -= mean; xv[i].w -= mean;
        vv += xv[i].x * xv[i].x + xv[i].y * xv[i].y
            + xv[i].z * xv[i].z + xv[i].w * xv[i].w;
    }
#pragma unroll
    for (int o2 = 16; o2; o2 >>= 1) vv += __shfl_xor_sync(0xffffffffu, vv, o2);
    float inv = rsqrtf(vv * (1.0f / DMODEL) + LN_EPS);

#pragma unroll
    for (int i = 0; i < 4; i++) {
        int c = i * 128 + lane * 4;
        float4 gv = *(const float4*)&g[c];
        float4 bv = *(const float4*)&bb[c];
        float4 y;
        y.x = fmaf(xv[i].x * inv, gv.x, bv.x);
        y.y = fmaf(xv[i].y * inv, gv.y, bv.y);
        y.z = fmaf(xv[i].z * inv, gv.z, bv.z);
        y.w = fmaf(xv[i].w * inv, gv.w, bv.w);
        *(float4*)&h[base + c] = y;
        float4 yr = make_float4(tf32r(y.x), tf32r(y.y), tf32r(y.z), tf32r(y.w));
        *(float4*)&hr[base + c] = yr;
    }
}

/* ---------------- host driver ---------------- */
extern "C" void kernel_launch(void* const* d_in, const int* in_sizes, int n_in,
                              void* d_out, int out_size) {
    const int*   x    = (const int*)  d_in[0];
    const float* tok  = (const float*)d_in[1];
    const float* pos  = (const float*)d_in[2];
    const float* Wq   = (const float*)d_in[3];
    const float* Wk   = (const float*)d_in[4];
    const float* Wv   = (const float*)d_in[5];
    const float* Wo   = (const float*)d_in[6];
    const float* ln1g = (const float*)d_in[7];
    const float* ln1b = (const float*)d_in[8];
    const float* W1   = (const float*)d_in[9];
    const float* W2   = (const float*)d_in[10];
    const float* ln2g = (const float*)d_in[11];
    const float* ln2b = (const float*)d_in[12];
    const float* Wl   = (const float*)d_in[13];
    float* out = (float*)d_out;

    float *ph, *phr, *pq, *pk, *pv, *pa, *pt, *pff, *pw;
    cudaGetSymbolAddress((void**)&ph,  g_h);
    cudaGetSymbolAddress((void**)&phr, g_hr);
    cudaGetSymbolAddress((void**)&pq,  g_q);
    cudaGetSymbolAddress((void**)&pk,  g_k);
    cudaGetSymbolAddress((void**)&pv,  g_v);
    cudaGetSymbolAddress((void**)&pa,  g_a);
    cudaGetSymbolAddress((void**)&pt,  g_t);
    cudaGetSymbolAddress((void**)&pff, g_ff);
    cudaGetSymbolAddress((void**)&pw,  g_w);

    cudaFuncSetAttribute(attn_tc,    cudaFuncAttributeMaxDynamicSharedMemorySize, ATTN_SMEM);
    cudaFuncSetAttribute(gemm_tc<0>, cudaFuncAttributeMaxDynamicSharedMemorySize, G_SMEM_L);
    cudaFuncSetAttribute(gemm_tc<1>, cudaFuncAttributeMaxDynamicSharedMemorySize, G_SMEM_L);
    cudaFuncSetAttribute(gemm_sm<0>, cudaFuncAttributeMaxDynamicSharedMemorySize, G_SMEM_S);
    cudaFuncSetAttribute(gemm_qkv,   cudaFuncAttributeMaxDynamicSharedMemorySize, G_SMEM_S);

    prep_kernel<<<PB7 / 256, 256>>>(x, tok, pos,
        Wq, Wk, Wv, Wo, W1, W2, Wl, pw, (float2*)ph, (float2*)phr);

    for (int i = 0; i < NDEPTH; i++) {
        const float* wq = pw + WOFF_Q + (size_t)i * PLF_D;
        const float* wk = pw + WOFF_K + (size_t)i * PLF_D;
        const float* wv = pw + WOFF_V + (size_t)i * PLF_D;
        const float* wo = pw + WOFF_O + (size_t)i * PLF_D;
        const float* w1 = pw + WOFF_1 + (size_t)i * PLF_F;
        const float* w2 = pw + WOFF_2 + (size_t)i * PLF_F;

        gemm_qkv<<<dim3(DMODEL / 128, MROWS / 64, 3), 128, G_SMEM_S>>>(
            phr, wq, wk, wv, pq, pk, pv, DMODEL, DMODEL);

        attn_tc<<<dim3(SEQ / 64, NHEADS, NB), 128, ATTN_SMEM>>>(pq, pk, pv, pa);

        gemm_sm<0><<<dim3(DMODEL / 128, MROWS / 64), 128, G_SMEM_S>>>(pa, wo, pt, DMODEL, DMODEL);
        ln_res_kernel<<<MROWS / 8, 256>>>(ph, pt, ln1g + i * DMODEL, ln1b + i * DMODEL, phr);

        gemm_tc<1><<<dim3(DFFN / 128, MROWS / 128), 256, G_SMEM_L>>>(phr, w1, pff, DFFN, DMODEL);
        gemm_sm<0><<<dim3(DMODEL / 128, MROWS / 64), 128, G_SMEM_S>>>(pff, w2, pt, DMODEL, DFFN);
        ln_res_kernel<<<MROWS / 8, 256>>>(ph, pt, ln2g + i * DMODEL, ln2b + i * DMODEL, phr);
    }

    gemm_tc<0><<<dim3(VOCAB / 128, MROWS / 128), 256, G_SMEM_L>>>(phr, pw + WOFF_L, out, VOCAB, DMODEL);
}

// round 17
// speedup vs baseline: 1.4827x; 1.4827x over previous
#include <cuda_runtime.h>
#include <cuda_bf16.h>
#include <math.h>
#include <stdint.h>

#define NB      2
#define SEQ     2048
#define DMODEL  512
#define VOCAB   32000
#define NHEADS  8
#define DHEAD   64
#define DFFN    2048
#define NDEPTH  6
#define MROWS   (NB*SEQ)   /* 4096 */

#define RES_SCALE 1.86120971820393f
#define ATTN_SCALE 8.0f
#define LN_EPS 1e-5f

/* ---------------- scratch ---------------- */
__device__ float g_h [MROWS*DMODEL];
__device__ float g_hr[MROWS*DMODEL];
__device__ float g_q [MROWS*DMODEL];
__device__ float g_k [MROWS*DMODEL];
__device__ float g_v [MROWS*DMODEL];
__device__ float g_a [MROWS*DMODEL];
__device__ float g_t [MROWS*DMODEL];
__device__ float g_ff[MROWS*DFFN];

/* pair-interleaved packed weights (R12 layout) */
#define BLKF    4224
#define PLF_D   270336
#define PLF_F   1081344
#define WOFF_Q  0
#define WOFF_K  1622016
#define WOFF_V  3244032
#define WOFF_O  4866048
#define WOFF_1  6488064
#define WOFF_2  12976128
#define WOFF_L  19464192
#define WTOTAL  36360192
__device__ float g_w[WTOTAL];

__device__ __forceinline__ float tf32r(float x) {
    unsigned u;
    asm("cvt.rna.tf32.f32 %0, %1;" : "=r"(u) : "f"(x));
    return __uint_as_float(u);
}
__device__ __forceinline__ uint32_t smem_u32(const void* p) {
    uint32_t a;
    asm("{ .reg .u64 t; cvta.to.shared.u64 t, %1; cvt.u32.u64 %0, t; }" : "=r"(a) : "l"(p));
    return a;
}
__device__ __forceinline__ void cpa16(uint32_t dst, const void* src) {
    asm volatile("cp.async.cg.shared.global [%0], [%1], 16;" :: "r"(dst), "l"(src));
}
__device__ __forceinline__ void mma_tf32(float* d, const unsigned* a, unsigned b0, unsigned b1) {
    asm volatile(
        "mma.sync.aligned.m16n8k8.row.col.f32.tf32.tf32.f32 "
        "{%0,%1,%2,%3},{%4,%5,%6,%7},{%8,%9},{%0,%1,%2,%3};"
        : "+f"(d[0]), "+f"(d[1]), "+f"(d[2]), "+f"(d[3])
        : "r"(a[0]), "r"(a[1]), "r"(a[2]), "r"(a[3]), "r"(b0), "r"(b1));
}

/* ======== prep: pack weights + embed ======== */
#define PB0  811008u
#define PB1  1622016u
#define PB2  2433024u
#define PB3  3244032u
#define PB4  6488064u
#define PB5  9732096u
#define PB6  18180096u
#define PB7  19228672u

__device__ __forceinline__ void wpack(const float* __restrict__ src, float2* __restrict__ dst,
                                      unsigned rel, int K, int N, unsigned blocksPerLayer) {
    unsigned block = rel / 2112u, w = rel - block * 2112u;
    unsigned row = w / 132u, np = w - row * 132u;
    unsigned nb128 = (unsigned)N >> 7;
    unsigned lay = block / blocksPerLayer, bl = block - lay * blocksPerLayer;
    unsigned s = bl / nb128, nb = bl - s * nb128;
    unsigned ks = row >> 2, tg = row & 3;
    float2 o = make_float2(0.0f, 0.0f);
    if (np < 128u) {
        size_t base = (size_t)lay * K * N + (size_t)(s * 32 + ks * 8 + tg) * N + nb * 128 + np;
        o.x = tf32r(src[base]);
        o.y = tf32r(src[base + (size_t)4 * N]);
    }
    dst[rel] = o;
}

__global__ __launch_bounds__(256) void prep_kernel(
    const int* __restrict__ x, const float* __restrict__ tok, const float* __restrict__ pos,
    const float* __restrict__ Wq, const float* __restrict__ Wk, const float* __restrict__ Wv,
    const float* __restrict__ Wo, const float* __restrict__ W1, const float* __restrict__ W2,
    const float* __restrict__ Wl, float* __restrict__ wout,
    float2* __restrict__ h2, float2* __restrict__ hr2) {
    unsigned i = blockIdx.x * 256 + threadIdx.x;
    if (i < PB6) {
        if (i < PB3) {
            if (i < PB0)      wpack(Wq, (float2*)(wout + WOFF_Q), i,        DMODEL, DMODEL, 64);
            else if (i < PB1) wpack(Wk, (float2*)(wout + WOFF_K), i - PB0,  DMODEL, DMODEL, 64);
            else if (i < PB2) wpack(Wv, (float2*)(wout + WOFF_V), i - PB1,  DMODEL, DMODEL, 64);
            else              wpack(Wo, (float2*)(wout + WOFF_O), i - PB2,  DMODEL, DMODEL, 64);
        } else if (i < PB4)   wpack(W1, (float2*)(wout + WOFF_1), i - PB3,  DMODEL, DFFN,   256);
        else if (i < PB5)     wpack(W2, (float2*)(wout + WOFF_2), i - PB4,  DFFN,   DMODEL, 256);
        else                  wpack(Wl, (float2*)(wout + WOFF_L), i - PB5,  DMODEL, VOCAB,  4000);
    } else {
        unsigned e = i - PB6;
        int row = e >> 8;
        int d2  = e & 255;
        int n   = row & (SEQ - 1);
        const float* tp = tok + (size_t)x[row] * DMODEL + d2 * 2;
        const float* pp = pos + (size_t)n * DMODEL + d2 * 2;
        float2 v = make_float2(tp[0] + pp[0], tp[1] + pp[1]);
        h2[e] = v;
        hr2[e] = make_float2(tf32r(v.x), tf32r(v.y));
    }
}

/* ================= TF32 mma.sync GEMM, 3-stage cp.async (R15) ============ */
#define AST     36
#define G_SMEM_L (3*(128*AST+BLKF)*4)    /* 105984 B */
#define G_SMEM_S (3*(64*AST+BLKF)*4)     /*  78336 B */

#define GSTAGE(slot, k0, BMv, Tv, ASTGv)                                         \
    do {                                                                         \
        uint32_t as_ = sb + (uint32_t)(slot) * ((ASTGv + BLKF) * 4);             \
        uint32_t bs_ = as_ + ASTGv * 4;                                          \
        _Pragma("unroll")                                                        \
        for (int it_ = 0; it_ < BMv * 8 / Tv; it_++) {                           \
            int id_ = tid + it_ * Tv;                                            \
            int r_ = id_ >> 3, c4_ = (id_ & 7) * 4;                              \
            cpa16(as_ + (r_ * AST + c4_) * 4,                                    \
                  A + (size_t)(bm + r_) * K + (k0) + c4_);                       \
        }                                                                        \
        const float* Bb_ = B + ((size_t)((k0) >> 5) * nb128 + blockIdx.x) * BLKF; \
        _Pragma("unroll")                                                        \
        for (int it_ = 0; it_ < (1056 + Tv - 1) / Tv; it_++) {                   \
            int id_ = tid + it_ * Tv;                                            \
            if (id_ < 1056) cpa16(bs_ + id_ * 16, Bb_ + id_ * 4);                \
        }                                                                        \
        asm volatile("cp.async.commit_group;" ::: "memory");                     \
    } while (0)

template<int EPI, int BM, int T>
__device__ __forceinline__ void gemm_body(const float* __restrict__ A,
                                          const float* __restrict__ B,
                                          float* __restrict__ C,
                                          int N, int K, float* sm) {
    constexpr int ASTG   = BM * AST;
    constexpr int STAGEF = ASTG + BLKF;

    int tid = threadIdx.x;
    int warp = tid >> 5, lane = tid & 31;
    int wm = warp >> 1, wn = warp & 1;
    int g = lane >> 2, tg = lane & 3;
    int bm = blockIdx.y * BM;
    int bn = blockIdx.x * 128;
    int nb128 = N >> 7;

    uint32_t sb = smem_u32(sm);

    float acc[2][8][4];
#pragma unroll
    for (int i = 0; i < 2; i++)
#pragma unroll
        for (int j = 0; j < 8; j++)
#pragma unroll
            for (int t = 0; t < 4; t++) acc[i][j][t] = 0.0f;

    int nIter = K >> 5;

    GSTAGE(0, 0, BM, T, ASTG);
    if (nIter > 1) GSTAGE(1, 32, BM, T, ASTG);
    else asm volatile("cp.async.commit_group;" ::: "memory");

    for (int it = 0; it < nIter; it++) {
        asm volatile("cp.async.wait_group 1;" ::: "memory");
        __syncthreads();
        if (it + 2 < nIter) GSTAGE((it + 2) % 3, (it + 2) * 32, BM, T, ASTG);
        else asm volatile("cp.async.commit_group;" ::: "memory");

        int slot = it % 3;
        const float*  as = sm + slot * STAGEF;
        const float2* b2 = (const float2*)(as + ASTG);

#pragma unroll
        for (int ks = 0; ks < 4; ks++) {
            int k8 = ks * 8;
            int rb = (ks * 4 + tg) * 132;
            unsigned af[2][4];
#pragma unroll
            for (int i = 0; i < 2; i++) {
                int mr = wm * 32 + i * 16 + g;
                af[i][0] = __float_as_uint(as[mr * AST + k8 + tg]);
                af[i][1] = __float_as_uint(as[(mr + 8) * AST + k8 + tg]);
                af[i][2] = __float_as_uint(as[mr * AST + k8 + tg + 4]);
                af[i][3] = __float_as_uint(as[(mr + 8) * AST + k8 + tg + 4]);
            }
#pragma unroll
            for (int j = 0; j < 8; j++) {
                int nc = wn * 64 + j * 8 + g;
                float2 bv = b2[rb + nc];
                unsigned b0 = __float_as_uint(bv.x);
                unsigned b1 = __float_as_uint(bv.y);
                mma_tf32(acc[0][j], af[0], b0, b1);
                mma_tf32(acc[1][j], af[1], b0, b1);
            }
        }
    }

    if (EPI == 2) {
        __syncthreads();
#pragma unroll
        for (int i = 0; i < 2; i++) {
            float ss0 = 0.0f, ss1 = 0.0f;
#pragma unroll
            for (int j = 0; j < 8; j++) {
                ss0 += acc[i][j][0] * acc[i][j][0] + acc[i][j][1] * acc[i][j][1];
                ss1 += acc[i][j][2] * acc[i][j][2] + acc[i][j][3] * acc[i][j][3];
            }
            ss0 += __shfl_xor_sync(0xffffffffu, ss0, 1);
            ss0 += __shfl_xor_sync(0xffffffffu, ss0, 2);
            ss1 += __shfl_xor_sync(0xffffffffu, ss1, 1);
            ss1 += __shfl_xor_sync(0xffffffffu, ss1, 2);
            float n0 = 1.0f / fmaxf(sqrtf(ss0), 1e-12f);
            float n1 = 1.0f / fmaxf(sqrtf(ss1), 1e-12f);
#pragma unroll
            for (int j = 0; j < 8; j++) {
                acc[i][j][0] *= n0; acc[i][j][1] *= n0;
                acc[i][j][2] *= n1; acc[i][j][3] *= n1;
            }
        }
    }

#pragma unroll
    for (int i = 0; i < 2; i++) {
        int r0 = bm + wm * 32 + i * 16 + g;
#pragma unroll
        for (int j = 0; j < 8; j++) {
            int col = bn + wn * 64 + j * 8 + tg * 2;
            float v0 = acc[i][j][0], v1 = acc[i][j][1];
            float v2 = acc[i][j][2], v3 = acc[i][j][3];
            if (EPI == 1) {
                v0 = tf32r(0.5f * v0 * (1.0f + erff(v0 * 0.70710678118654752f)));
                v1 = tf32r(0.5f * v1 * (1.0f + erff(v1 * 0.70710678118654752f)));
                v2 = tf32r(0.5f * v2 * (1.0f + erff(v2 * 0.70710678118654752f)));
                v3 = tf32r(0.5f * v3 * (1.0f + erff(v3 * 0.70710678118654752f)));
            } else if (EPI == 2 || EPI == 3) {
                v0 = tf32r(v0); v1 = tf32r(v1); v2 = tf32r(v2); v3 = tf32r(v3);
            }
            *(float2*)&C[(size_t)r0 * N + col]       = make_float2(v0, v1);
            *(float2*)&C[(size_t)(r0 + 8) * N + col] = make_float2(v2, v3);
        }
    }
}

template<int EPI>
__global__ __launch_bounds__(256, 2) void gemm_tc(const float* __restrict__ A,
                                                  const float* __restrict__ B,
                                                  float* __restrict__ C, int N, int K) {
    extern __shared__ float sm[];
    gemm_body<EPI, 128, 256>(A, B, C, N, K, sm);
}

template<int EPI>
__global__ __launch_bounds__(128, 2) void gemm_sm(const float* __restrict__ A,
                                                  const float* __restrict__ B,
                                                  float* __restrict__ C, int N, int K) {
    extern __shared__ float sm[];
    gemm_body<EPI, 64, 128>(A, B, C, N, K, sm);
}

__global__ __launch_bounds__(128, 2) void gemm_qkv(const float* __restrict__ A,
                                                   const float* __restrict__ B0,
                                                   const float* __restrict__ B1,
                                                   const float* __restrict__ B2,
                                                   float* __restrict__ C0,
                                                   float* __restrict__ C1,
                                                   float* __restrict__ C2,
                                                   int N, int K) {
    extern __shared__ float sm[];
    if (blockIdx.z == 0)      gemm_body<2, 64, 128>(A, B0, C0, N, K, sm);
    else if (blockIdx.z == 1) gemm_body<2, 64, 128>(A, B1, C1, N, K, sm);
    else                      gemm_body<3, 64, 128>(A, B2, C2, N, K, sm);
}

/* ====== logits GEMM: 128 thr, 4 warps 2x2, warp tile 64x64 (ILP variant) ==
   acc[4][8][4] = 128 regs of independent accumulators per warp.
   Per k8: 16 a-LDS.32 + 8 b-LDS.64 feed 32 MMAs (0.75 LDS/MMA). */
__global__ __launch_bounds__(128) void gemm_lg(const float* __restrict__ A,
                                               const float* __restrict__ B,
                                               float* __restrict__ C, int N, int K) {
    extern __shared__ float sm[];
    constexpr int BM = 128, T = 128;
    constexpr int ASTG   = BM * AST;
    constexpr int STAGEF = ASTG + BLKF;

    int tid = threadIdx.x;
    int warp = tid >> 5, lane = tid & 31;
    int wm = warp >> 1, wn = warp & 1;
    int g = lane >> 2, tg = lane & 3;
    int bm = blockIdx.y * BM;
    int bn = blockIdx.x * 128;
    int nb128 = N >> 7;

    uint32_t sb = smem_u32(sm);

    float acc[4][8][4];
#pragma unroll
    for (int i = 0; i < 4; i++)
#pragma unroll
        for (int j = 0; j < 8; j++)
#pragma unroll
            for (int t = 0; t < 4; t++) acc[i][j][t] = 0.0f;

    int nIter = K >> 5;

    GSTAGE(0, 0, BM, T, ASTG);
    if (nIter > 1) GSTAGE(1, 32, BM, T, ASTG);
    else asm volatile("cp.async.commit_group;" ::: "memory");

    for (int it = 0; it < nIter; it++) {
        asm volatile("cp.async.wait_group 1;" ::: "memory");
        __syncthreads();
        if (it + 2 < nIter) GSTAGE((it + 2) % 3, (it + 2) * 32, BM, T, ASTG);
        else asm volatile("cp.async.commit_group;" ::: "memory");

        int slot = it % 3;
        const float*  as = sm + slot * STAGEF;
        const float2* b2 = (const float2*)(as + ASTG);

#pragma unroll
        for (int ks = 0; ks < 4; ks++) {
            int k8 = ks * 8;
            int rb = (ks * 4 + tg) * 132;
            unsigned af[4][4];
#pragma unroll
            for (int i = 0; i < 4; i++) {
                int mr = wm * 64 + i * 16 + g;
                af[i][0] = __float_as_uint(as[mr * AST + k8 + tg]);
                af[i][1] = __float_as_uint(as[(mr + 8) * AST + k8 + tg]);
                af[i][2] = __float_as_uint(as[mr * AST + k8 + tg + 4]);
                af[i][3] = __float_as_uint(as[(mr + 8) * AST + k8 + tg + 4]);
            }
#pragma unroll
            for (int j = 0; j < 8; j++) {
                int nc = wn * 64 + j * 8 + g;
                float2 bv = b2[rb + nc];
                unsigned b0 = __float_as_uint(bv.x);
                unsigned b1 = __float_as_uint(bv.y);
                mma_tf32(acc[0][j], af[0], b0, b1);
                mma_tf32(acc[1][j], af[1], b0, b1);
                mma_tf32(acc[2][j], af[2], b0, b1);
                mma_tf32(acc[3][j], af[3], b0, b1);
            }
        }
    }

#pragma unroll
    for (int i = 0; i < 4; i++) {
        int r0 = bm + wm * 64 + i * 16 + g;
#pragma unroll
        for (int j = 0; j < 8; j++) {
            int col = bn + wn * 64 + j * 8 + tg * 2;
            *(float2*)&C[(size_t)r0 * N + col]       = make_float2(acc[i][j][0], acc[i][j][1]);
            *(float2*)&C[(size_t)(r0 + 8) * N + col] = make_float2(acc[i][j][2], acc[i][j][3]);
        }
    }
}

/* ================= TF32 flash attention (R15, kept) ================= */
#define KPAD 68
#define VPAD 72
#define KS_F (64*KPAD)
#define VS_F (64*VPAD)
#define ATTN_SMEM ((2*KS_F + 2*VS_F + 64*72) * 4)

__global__ __launch_bounds__(128, 2) void attn_tc(const float* __restrict__ q,
                                                  const float* __restrict__ k,
                                                  const float* __restrict__ v,
                                                  float* __restrict__ o) {
    extern __shared__ float sm[];
    float* Ks0 = sm;
    float* Vs0 = sm + 2 * KS_F;
    float* Ps  = sm + 2 * KS_F + 2 * VS_F;
    uint32_t sb = smem_u32(sm);

    int qt = gridDim.x - 1 - blockIdx.x;
    int hh = blockIdx.y, b = blockIdx.z;
    int tid = threadIdx.x, warp = tid >> 5, lane = tid & 31;
    int g = lane >> 2, tg = lane & 3;

    unsigned qf[8][4];
    const float* qbase = q + (size_t)(b * SEQ + qt * 64 + warp * 16 + g) * DMODEL + hh * 64;
#pragma unroll
    for (int kk = 0; kk < 8; kk++) {
        qf[kk][0] = __float_as_uint(qbase[kk * 8 + tg]);
        qf[kk][1] = __float_as_uint(qbase[(size_t)8 * DMODEL + kk * 8 + tg]);
        qf[kk][2] = __float_as_uint(qbase[kk * 8 + tg + 4]);
        qf[kk][3] = __float_as_uint(qbase[(size_t)8 * DMODEL + kk * 8 + tg + 4]);
    }

    float oa[8][4];
#pragma unroll
    for (int j = 0; j < 8; j++)
#pragma unroll
        for (int t = 0; t < 4; t++) oa[j][t] = 0.0f;
    float l0 = 0.0f, l1 = 0.0f;

    int prow0 = (warp * 16 + g) * 72;
    int prow1 = (warp * 16 + g + 8) * 72;

#define ASTAGE_TILE(kt_, bb_)                                                    \
    do {                                                                         \
        uint32_t ka_ = sb + (uint32_t)(bb_) * (KS_F * 4);                        \
        uint32_t va_ = sb + (2 * KS_F + (bb_) * VS_F) * 4;                       \
        _Pragma("unroll")                                                        \
        for (int it_ = 0; it_ < 8; it_++) {                                      \
            int i_ = tid + it_ * 128;                                            \
            int r_ = i_ >> 4, c4_ = (i_ & 15) * 4;                               \
            size_t gg_ = (size_t)(b * SEQ + (kt_) * 64 + r_) * DMODEL + hh * 64 + c4_; \
            cpa16(ka_ + (r_ * KPAD + c4_) * 4, k + gg_);                         \
            cpa16(va_ + (r_ * VPAD + c4_) * 4, v + gg_);                         \
        }                                                                        \
        asm volatile("cp.async.commit_group;" ::: "memory");                     \
    } while (0)

    ASTAGE_TILE(0, 0);

    for (int kt = 0; kt <= qt; kt++) {
        int bb = kt & 1;
        asm volatile("cp.async.wait_group 0;" ::: "memory");
        __syncthreads();
        if (kt < qt) ASTAGE_TILE(kt + 1, bb ^ 1);

        const float* Ks = Ks0 + bb * KS_F;
        const float* Vs = Vs0 + bb * VS_F;

        float s[8][4];
#pragma unroll
        for (int j = 0; j < 8; j++)
#pragma unroll
            for (int t = 0; t < 4; t++) s[j][t] = 0.0f;
#pragma unroll
        for (int kk = 0; kk < 8; kk++) {
            int d0 = kk * 8 + tg, d1 = d0 + 4;
#pragma unroll
            for (int j = 0; j < 8; j++) {
                const float* krow = Ks + (j * 8 + g) * KPAD;
                unsigned b0 = __float_as_uint(krow[d0]);
                unsigned b1 = __float_as_uint(krow[d1]);
                mma_tf32(s[j], qf[kk], b0, b1);
            }
        }

        if (kt == qt) {
            int r0 = warp * 16 + g, r1 = r0 + 8;
#pragma unroll
            for (int j = 0; j < 8; j++) {
                int c0 = j * 8 + tg * 2, c1 = c0 + 1;
                if (c0 > r0) s[j][0] = -1e30f;
                if (c1 > r0) s[j][1] = -1e30f;
                if (c0 > r1) s[j][2] = -1e30f;
                if (c1 > r1) s[j][3] = -1e30f;
            }
        }

        float sum0 = 0.0f, sum1 = 0.0f;
#pragma unroll
        for (int j = 0; j < 8; j++) {
            int c0 = j * 8 + tg * 2;
            float e0 = __expf(fmaf(s[j][0], ATTN_SCALE, -ATTN_SCALE));
            float e1 = __expf(fmaf(s[j][1], ATTN_SCALE, -ATTN_SCALE));
            float e2 = __expf(fmaf(s[j][2], ATTN_SCALE, -ATTN_SCALE));
            float e3 = __expf(fmaf(s[j][3], ATTN_SCALE, -ATTN_SCALE));
            sum0 += e0 + e1;
            sum1 += e2 + e3;
            *(float2*)&Ps[prow0 + c0] = make_float2(e0, e1);
            *(float2*)&Ps[prow1 + c0] = make_float2(e2, e3);
        }
        sum0 += __shfl_xor_sync(0xffffffffu, sum0, 1);
        sum0 += __shfl_xor_sync(0xffffffffu, sum0, 2);
        sum1 += __shfl_xor_sync(0xffffffffu, sum1, 1);
        sum1 += __shfl_xor_sync(0xffffffffu, sum1, 2);
        l0 += sum0;
        l1 += sum1;
        __syncwarp();

#pragma unroll
        for (int kk = 0; kk < 8; kk++) {
            unsigned a[4];
            a[0] = __float_as_uint(Ps[prow0 + kk * 8 + tg]);
            a[1] = __float_as_uint(Ps[prow1 + kk * 8 + tg]);
            a[2] = __float_as_uint(Ps[prow0 + kk * 8 + tg + 4]);
            a[3] = __float_as_uint(Ps[prow1 + kk * 8 + tg + 4]);
#pragma unroll
            for (int j = 0; j < 8; j++) {
                unsigned b0 = __float_as_uint(Vs[(kk * 8 + tg)     * VPAD + j * 8 + g]);
                unsigned b1 = __float_as_uint(Vs[(kk * 8 + tg + 4) * VPAD + j * 8 + g]);
                mma_tf32(oa[j], a, b0, b1);
            }
        }
    }
#undef ASTAGE_TILE

    float inv0 = 1.0f / l0, inv1 = 1.0f / l1;
    size_t orow0 = (size_t)(b * SEQ + qt * 64 + warp * 16 + g) * DMODEL + hh * 64;
    size_t orow1 = orow0 + (size_t)8 * DMODEL;
#pragma unroll
    for (int j = 0; j < 8; j++) {
        int c0 = j * 8 + tg * 2;
        *(float2*)&o[orow0 + c0] = make_float2(tf32r(oa[j][0] * inv0), tf32r(oa[j][1] * inv0));
        *(float2*)&o[orow1 + c0] = make_float2(tf32r(oa[j][2] * inv1), tf32r(oa[j][3] * inv1));
    }
}

/* ---------------- residual + LayerNorm: one warp per row ---------------- */
__global__ __launch_bounds__(256) void ln_res_kernel(
        float* __restrict__ h, const float* __restrict__ a,
        const float* __restrict__ g, const float* __restrict__ bb,
        float* __restrict__ hr) {
    int warp = threadIdx.x >> 5, lane = threadIdx.x & 31;
    int row = blockIdx.x * 8 + warp;
    size_t base = (size_t)row * DMODEL;

    float4 xv[4];
    float s = 0.0f;
#pragma unroll
    for (int i = 0; i < 4; i++) {
        int c = i * 128 + lane * 4;
        float4 hv = *(const float4*)&h[base + c];
        float4 av = *(const float4*)&a[base + c];
        xv[i].x = fmaf(RES_SCALE, hv.x, av.x);
        xv[i].y = fmaf(RES_SCALE, hv.y, av.y);
        xv[i].z = fmaf(RES_SCALE, hv.z, av.z);
        xv[i].w = fmaf(RES_SCALE, hv.w, av.w);
        s += (xv[i].x + xv[i].y) + (xv[i].z + xv[i].w);
    }
#pragma unroll
    for (int o2 = 16; o2; o2 >>= 1) s += __shfl_xor_sync(0xffffffffu, s, o2);
    float mean = s * (1.0f / DMODEL);

    float vv = 0.0f;
#pragma unroll
    for (int i = 0; i < 4; i++) {
        xv[i].x -= mean; xv[i].y -= mean; xv[i].z -= mean; xv[i].w -= mean;
        vv += xv[i].x * xv[i].x + xv[i].y * xv[i].y
            + xv[i].z * xv[i].z + xv[i].w * xv[i].w;
    }
#pragma unroll
    for (int o2 = 16; o2; o2 >>= 1) vv += __shfl_xor_sync(0xffffffffu, vv, o2);
    float inv = rsqrtf(vv * (1.0f / DMODEL) + LN_EPS);

#pragma unroll
    for (int i = 0; i < 4; i++) {
        int c = i * 128 + lane * 4;
        float4 gv = *(const float4*)&g[c];
        float4 bv = *(const float4*)&bb[c];
        float4 y;
        y.x = fmaf(xv[i].x * inv, gv.x, bv.x);
        y.y = fmaf(xv[i].y * inv, gv.y, bv.y);
        y.z = fmaf(xv[i].z * inv, gv.z, bv.z);
        y.w = fmaf(xv[i].w * inv, gv.w, bv.w);
        *(float4*)&h[base + c] = y;
        float4 yr = make_float4(tf32r(y.x), tf32r(y.y), tf32r(y.z), tf32r(y.w));
        *(float4*)&hr[base + c] = yr;
    }
}

/* ---------------- host driver ---------------- */
extern "C" void kernel_launch(void* const* d_in, const int* in_sizes, int n_in,
                              void* d_out, int out_size) {
    const int*   x    = (const int*)  d_in[0];
    const float* tok  = (const float*)d_in[1];
    const float* pos  = (const float*)d_in[2];
    const float* Wq   = (const float*)d_in[3];
    const float* Wk   = (const float*)d_in[4];
    const float* Wv   = (const float*)d_in[5];
    const float* Wo   = (const float*)d_in[6];
    const float* ln1g = (const float*)d_in[7];
    const float* ln1b = (const float*)d_in[8];
    const float* W1   = (const float*)d_in[9];
    const float* W2   = (const float*)d_in[10];
    const float* ln2g = (const float*)d_in[11];
    const float* ln2b = (const float*)d_in[12];
    const float* Wl   = (const float*)d_in[13];
    float* out = (float*)d_out;

    float *ph, *phr, *pq, *pk, *pv, *pa, *pt, *pff, *pw;
    cudaGetSymbolAddress((void**)&ph,  g_h);
    cudaGetSymbolAddress((void**)&phr, g_hr);
    cudaGetSymbolAddress((void**)&pq,  g_q);
    cudaGetSymbolAddress((void**)&pk,  g_k);
    cudaGetSymbolAddress((void**)&pv,  g_v);
    cudaGetSymbolAddress((void**)&pa,  g_a);
    cudaGetSymbolAddress((void**)&pt,  g_t);
    cudaGetSymbolAddress((void**)&pff, g_ff);
    cudaGetSymbolAddress((void**)&pw,  g_w);

    cudaFuncSetAttribute(attn_tc,    cudaFuncAttributeMaxDynamicSharedMemorySize, ATTN_SMEM);
    cudaFuncSetAttribute(gemm_tc<0>, cudaFuncAttributeMaxDynamicSharedMemorySize, G_SMEM_L);
    cudaFuncSetAttribute(gemm_tc<1>, cudaFuncAttributeMaxDynamicSharedMemorySize, G_SMEM_L);
    cudaFuncSetAttribute(gemm_lg,    cudaFuncAttributeMaxDynamicSharedMemorySize, G_SMEM_L);
    cudaFuncSetAttribute(gemm_sm<0>, cudaFuncAttributeMaxDynamicSharedMemorySize, G_SMEM_S);
    cudaFuncSetAttribute(gemm_qkv,   cudaFuncAttributeMaxDynamicSharedMemorySize, G_SMEM_S);

    prep_kernel<<<PB7 / 256, 256>>>(x, tok, pos,
        Wq, Wk, Wv, Wo, W1, W2, Wl, pw, (float2*)ph, (float2*)phr);

    for (int i = 0; i < NDEPTH; i++) {
        const float* wq = pw + WOFF_Q + (size_t)i * PLF_D;
        const float* wk = pw + WOFF_K + (size_t)i * PLF_D;
        const float* wv = pw + WOFF_V + (size_t)i * PLF_D;
        const float* wo = pw + WOFF_O + (size_t)i * PLF_D;
        const float* w1 = pw + WOFF_1 + (size_t)i * PLF_F;
        const float* w2 = pw + WOFF_2 + (size_t)i * PLF_F;

        gemm_qkv<<<dim3(DMODEL / 128, MROWS / 64, 3), 128, G_SMEM_S>>>(
            phr, wq, wk, wv, pq, pk, pv, DMODEL, DMODEL);

        attn_tc<<<dim3(SEQ / 64, NHEADS, NB), 128, ATTN_SMEM>>>(pq, pk, pv, pa);

        gemm_sm<0><<<dim3(DMODEL / 128, MROWS / 64), 128, G_SMEM_S>>>(pa, wo, pt, DMODEL, DMODEL);
        ln_res_kernel<<<MROWS / 8, 256>>>(ph, pt, ln1g + i * DMODEL, ln1b + i * DMODEL, phr);

        gemm_tc<1><<<dim3(DFFN / 128, MROWS / 128), 256, G_SMEM_L>>>(phr, w1, pff, DFFN, DMODEL);
        gemm_sm<0><<<dim3(DMODEL / 128, MROWS / 64), 128, G_SMEM_S>>>(pff, w2, pt, DMODEL, DFFN);
        ln_res_kernel<<<MROWS / 8, 256>>>(ph, pt, ln2g + i * DMODEL, ln2b + i * DMODEL, phr);
    }

    gemm_lg<<<dim3(VOCAB / 128, MROWS / 128), 128, G_SMEM_L>>>(phr, pw + WOFF_L, out, VOCAB, DMODEL);
}